// round 9
// baseline (speedup 1.0000x reference)
#include <cuda_runtime.h>
#include <cuda_bf16.h>
#include <cstdint>

#define TT 16
#define NU 4096
#define EE 128
#define HH 128
#define G4 512
#define LPATH 32
#define NPATH 1024
#define NB 8
#define VOCAB 16384

typedef unsigned long long u64;

__device__ __forceinline__ uint32_t smem_to_u32(const void* p) {
    uint32_t a;
    asm("{ .reg .u64 t; cvta.to.shared.u64 t, %1; cvt.u32.u64 %0, t; }" : "=r"(a) : "l"(p));
    return a;
}
#define LDSM_X4(r, addr) \
    asm volatile("ldmatrix.sync.aligned.m8n8.x4.shared.b16 {%0,%1,%2,%3}, [%4];" \
        : "=r"((r)[0]), "=r"((r)[1]), "=r"((r)[2]), "=r"((r)[3]) : "r"(addr))
__device__ __forceinline__ void mma16816(float* c, const uint32_t* a, uint32_t b0, uint32_t b1) {
    asm volatile("mma.sync.aligned.m16n8k16.row.col.f32.bf16.bf16.f32 "
        "{%0,%1,%2,%3}, {%4,%5,%6,%7}, {%8,%9}, {%0,%1,%2,%3};"
        : "+f"(c[0]), "+f"(c[1]), "+f"(c[2]), "+f"(c[3])
        : "r"(a[0]), "r"(a[1]), "r"(a[2]), "r"(a[3]), "r"(b0), "r"(b1));
}
__device__ __forceinline__ void ffma2(u64& d, u64 a, u64 b) {
    asm("fma.rn.f32x2 %0, %1, %2, %0;" : "+l"(d) : "l"(a), "l"(b));
}
__device__ __forceinline__ u64 dup2(float x) {
    u64 r; asm("mov.b64 %0, {%1, %1};" : "=l"(r) : "f"(x)); return r;
}
#define CP_ASYNC16(dst_u32, src_ptr) \
    asm volatile("cp.async.cg.shared.global [%0], [%1], 16;" :: "r"(dst_u32), "l"(src_ptr))
#define CP_COMMIT asm volatile("cp.async.commit_group;" ::: "memory")
#define CP_WAIT0  asm volatile("cp.async.wait_group 0;" ::: "memory")

// ============ device scratch ============
__device__ int   g_tok_len[NU];
__device__ int   g_p_len[NPATH], g_p_fe[NPATH], g_p_off[NPATH], g_p_un[NPATH];
__device__ float g_VTf[VOCAB * G4], g_VTb[VOCAB * G4];
__device__ float g_PTf[NU * G4],    g_PTb[NU * G4];
__device__ float g_lin[TT * NU * EE];
__device__ float g_WhT[4][HH * G4];
__device__ float g_zero[G4];
__device__ __nv_bfloat16 g_emb_h[VOCAB * EE],  g_emb_l[VOCAB * EE];
__device__ __nv_bfloat16 g_Hcat_h[TT * NU * 2 * HH], g_Hcat_l[TT * NU * 2 * HH];
__device__ __nv_bfloat16 g_tf_h[NU * EE], g_tf_l[NU * EE];
__device__ __nv_bfloat16 g_Hp_h[LPATH * NPATH * 2 * HH], g_Hp_l[LPATH * NPATH * 2 * HH];
__device__ __nv_bfloat16 g_Wih[4][G4 * EE], g_Wil[4][G4 * EE];
__device__ __nv_bfloat16 g_W2h[2][EE * 2 * HH], g_W2l[2][EE * 2 * HH];

// ============ setup kernels ============
__global__ void k_tok_len(const int* __restrict__ units) {
    int n = blockIdx.x * blockDim.x + threadIdx.x;
    if (n >= NU) return;
    int len = TT;
    for (int t = 0; t < TT; t++) if (units[t * NU + n] == 0) { len = t; break; }
    g_tok_len[n] = len;
}
__global__ void k_transpose4(const float* __restrict__ W0, const float* __restrict__ W1,
                             const float* __restrict__ W2, const float* __restrict__ W3) {
    int w = blockIdx.y;
    const float* W = (w == 0) ? W0 : (w == 1) ? W1 : (w == 2) ? W2 : W3;
    int idx = blockIdx.x * blockDim.x + threadIdx.x;
    if (idx >= G4 * HH) return;
    int j = idx >> 7, k = idx & 127;
    g_WhT[w][k * G4 + j] = W[idx];
}
__global__ void k_plen(const int* __restrict__ paths,
                       const int* __restrict__ upd, const int* __restrict__ ppd) {
    int p = blockIdx.x * blockDim.x + threadIdx.x;
    if (p >= NPATH) return;
    int dd = NB - 1, cum = 0;
    for (int i = 0; i < NB; i++) { int nx = cum + ppd[i]; if (p >= cum && p < nx) { dd = i; break; } cum = nx; }
    int off = 0;
    for (int i = 0; i < dd; i++) off += upd[i];
    int un = upd[dd];
    int fe = LPATH;
    for (int t = 0; t < LPATH; t++) if (paths[t * NPATH + p] == -1) { fe = t; break; }
    int plen = LPATH;
    for (int t = 0; t < LPATH; t++) {
        bool msk;
        if (t >= fe) msk = true;
        else { int v = paths[t * NPATH + p]; msk = (v < 0) || (v > un); }
        if (msk) { plen = t; break; }
    }
    g_p_len[p] = plen; g_p_fe[p] = fe; g_p_off[p] = off; g_p_un[p] = un;
}
__global__ void k_hilo(const float* __restrict__ src, __nv_bfloat16* __restrict__ hi,
                       __nv_bfloat16* __restrict__ lo, int n4) {
    int i = blockIdx.x * blockDim.x + threadIdx.x;
    if (i >= n4) return;
    float4 v = reinterpret_cast<const float4*>(src)[i];
    __nv_bfloat16 h0 = __float2bfloat16(v.x), h1 = __float2bfloat16(v.y);
    __nv_bfloat16 h2 = __float2bfloat16(v.z), h3 = __float2bfloat16(v.w);
    __nv_bfloat16 l0 = __float2bfloat16(v.x - __bfloat162float(h0));
    __nv_bfloat16 l1 = __float2bfloat16(v.y - __bfloat162float(h1));
    __nv_bfloat16 l2 = __float2bfloat16(v.z - __bfloat162float(h2));
    __nv_bfloat16 l3 = __float2bfloat16(v.w - __bfloat162float(h3));
    __nv_bfloat162* H = reinterpret_cast<__nv_bfloat162*>(hi);
    __nv_bfloat162* L = reinterpret_cast<__nv_bfloat162*>(lo);
    H[2 * i] = __nv_bfloat162(h0, h1); H[2 * i + 1] = __nv_bfloat162(h2, h3);
    L[2 * i] = __nv_bfloat162(l0, l1); L[2 * i + 1] = __nv_bfloat162(l2, l3);
}

// ============ warp-MMA split-bf16 GEMM (unchanged, passing) ============
template <int K>
__global__ __launch_bounds__(256) void k_mm2(
    const __nv_bfloat16* __restrict__ Ah, const __nv_bfloat16* __restrict__ Al,
    const __nv_bfloat16* __restrict__ Bh, const __nv_bfloat16* __restrict__ Bl,
    const float* __restrict__ bias, float* __restrict__ C, int Ntot)
{
    constexpr int LDS = 72;
    extern __shared__ __nv_bfloat16 sm[];
    __nv_bfloat16* sAh = sm;
    __nv_bfloat16* sAl = sAh + 128 * LDS;
    __nv_bfloat16* sBh = sAl + 128 * LDS;
    __nv_bfloat16* sBl = sBh + 128 * LDS;

    const int tid = threadIdx.x, lane = tid & 31, wid = tid >> 5;
    const int m0 = blockIdx.y * 128, n0 = blockIdx.x * 128;
    const int wm = (wid & 3) * 32, wn = (wid >> 2) * 64;
    const int g = lane >> 2, tg = lane & 3;
    const int seg = lane >> 3, i8 = lane & 7;
    const uint32_t sAh_b = smem_to_u32(sAh), sAl_b = smem_to_u32(sAl);
    const uint32_t sBh_b = smem_to_u32(sBh), sBl_b = smem_to_u32(sBl);

    float acc[2][8][4];
#pragma unroll
    for (int im = 0; im < 2; im++)
#pragma unroll
        for (int jn = 0; jn < 8; jn++)
#pragma unroll
            for (int q = 0; q < 4; q++) acc[im][jn][q] = 0.f;

    for (int kc = 0; kc < K; kc += 64) {
        if (kc) __syncthreads();
        {
            const __nv_bfloat16* srcs[4] = {Ah, Al, Bh, Bl};
            __nv_bfloat16* dsts[4] = {sAh, sAl, sBh, sBl};
            const int r0s[4] = {m0, m0, n0, n0};
#pragma unroll
            for (int t = 0; t < 4; t++) {
                for (int v = tid; v < 1024; v += 256) {
                    int row = v >> 3, q = (v & 7) * 8;
                    *reinterpret_cast<uint4*>(dsts[t] + row * LDS + q) =
                        *reinterpret_cast<const uint4*>(srcs[t] + (size_t)(r0s[t] + row) * K + kc + q);
                }
            }
        }
        __syncthreads();
#pragma unroll
        for (int ks = 0; ks < 4; ks++) {
            const int k0 = ks * 16;
            uint32_t ah[2][4], al[2][4];
#pragma unroll
            for (int im = 0; im < 2; im++) {
                int arow = wm + im * 16 + (seg & 1) * 8 + i8;
                int acol = k0 + (seg >> 1) * 8;
                LDSM_X4(ah[im], sAh_b + (uint32_t)(arow * LDS + acol) * 2u);
                LDSM_X4(al[im], sAl_b + (uint32_t)(arow * LDS + acol) * 2u);
            }
#pragma unroll
            for (int ip = 0; ip < 4; ip++) {
                int brow = wn + ip * 16 + (seg >> 1) * 8 + i8;
                int bcol = k0 + (seg & 1) * 8;
                uint32_t bh4[4], bl4[4];
                LDSM_X4(bh4, sBh_b + (uint32_t)(brow * LDS + bcol) * 2u);
                LDSM_X4(bl4, sBl_b + (uint32_t)(brow * LDS + bcol) * 2u);
#pragma unroll
                for (int im = 0; im < 2; im++) {
#pragma unroll
                    for (int hf = 0; hf < 2; hf++) {
                        float* c = acc[im][ip * 2 + hf];
                        mma16816(c, ah[im], bh4[2 * hf], bh4[2 * hf + 1]);
                        mma16816(c, al[im], bh4[2 * hf], bh4[2 * hf + 1]);
                        mma16816(c, ah[im], bl4[2 * hf], bl4[2 * hf + 1]);
                    }
                }
            }
        }
    }
#pragma unroll
    for (int im = 0; im < 2; im++) {
#pragma unroll
        for (int jn = 0; jn < 8; jn++) {
            int col = n0 + wn + jn * 8 + tg * 2;
            float b0v = bias[col], b1v = bias[col + 1];
            int row0 = m0 + wm + im * 16 + g;
            float2 v0 = make_float2(acc[im][jn][0] + b0v, acc[im][jn][1] + b1v);
            float2 v1 = make_float2(acc[im][jn][2] + b0v, acc[im][jn][3] + b1v);
            *reinterpret_cast<float2*>(C + (size_t)row0 * Ntot + col) = v0;
            *reinterpret_cast<float2*>(C + (size_t)(row0 + 8) * Ntot + col) = v1;
        }
    }
}

// ============ persistent BiLSTM: col-major split (4 cols x 16 rows per thread) ============
__device__ __forceinline__ float sigm(float x) { return 1.f / (1.f + expf(-x)); }

template <int MODE, int TSTEPS, int NSEQ, int ROWS, int THREADS>
__global__ __launch_bounds__(THREADS) void k_lstm(
    const int* __restrict__ idxmat,
    const float* __restrict__ tab_f, const float* __restrict__ tab_b,
    const float* __restrict__ bias_f, const float* __restrict__ bias_b,
    __nv_bfloat16* __restrict__ Hh, __nv_bfloat16* __restrict__ Hl)
{
    constexpr int NCP = 2048 / THREADS;
    extern __shared__ char dsm[];
    float* gates = reinterpret_cast<float*>(dsm);      // [ROWS*512]
    float* hs    = gates + ROWS * 512;                 // [ROWS*128]
    float* wbuf  = hs + ROWS * 128;                    // [2][8192]
    float* sbias = wbuf + 2 * 8192;                    // [512] (MODE1)
    int* slen = reinterpret_cast<int*>(sbias + (MODE ? 512 : 0));
    int* sfe  = slen + ROWS; int* soff = sfe + ROWS; int* sun = soff + ROWS;

    const int dir = blockIdx.y;
    const float* __restrict__ tab = dir ? tab_b : tab_f;
    const float* __restrict__ WhT = g_WhT[2 * MODE + dir];
    const int n0 = blockIdx.x * ROWS;
    const int tid = threadIdx.x, lane = tid & 31, wid = tid >> 5;
    const int cb = wid & 3, rg = wid >> 2;
    const int col0 = cb * 128 + lane * 4;
    const int rowbase = rg * 16;
    const uint32_t wbuf_a = smem_to_u32(wbuf);

    if (MODE == 1) {
        const float* b = dir ? bias_b : bias_f;
        for (int i = tid; i < G4; i += THREADS) sbias[i] = b[i];
    }
    for (int i = tid; i < ROWS * 32; i += THREADS)
        reinterpret_cast<float4*>(hs)[i] = make_float4(0.f, 0.f, 0.f, 0.f);
    if (tid < ROWS) {
        int n = n0 + tid;
        slen[tid] = MODE ? g_p_len[n] : g_tok_len[n];
        if (MODE) { sfe[tid] = g_p_fe[n]; soff[tid] = g_p_off[n]; sun[tid] = g_p_un[n]; }
    }
#pragma unroll
    for (int t = 0; t < NCP; t++)
        reinterpret_cast<float4*>(wbuf)[tid + t * THREADS] =
            reinterpret_cast<const float4*>(WhT)[tid + t * THREADS];
    __syncthreads();

    const int prow = tid >> 3, pc0 = (tid & 7) * 16;
    float cst[16];
#pragma unroll
    for (int j = 0; j < 16; j++) cst[j] = 0.f;

    for (int s = 0; s < TSTEPS; s++) {
        // -------- GEMV: gates = hs @ WhT --------
        u64 acc[16][2];
#pragma unroll
        for (int r = 0; r < 16; r++) { acc[r][0] = 0ull; acc[r][1] = 0ull; }
#pragma unroll
        for (int ch = 0; ch < 8; ch++) {
            {
                const int nxt = (ch + 1) & 7;
                const float4* src = reinterpret_cast<const float4*>(WhT + nxt * 8192);
                uint32_t dsta = wbuf_a + (uint32_t)(((ch + 1) & 1) * 8192) * 4u;
#pragma unroll
                for (int t = 0; t < NCP; t++)
                    CP_ASYNC16(dsta + (uint32_t)(tid + t * THREADS) * 16u, src + tid + t * THREADS);
                CP_COMMIT;
            }
            const float* wc = wbuf + (ch & 1) * 8192;
#pragma unroll
            for (int kg = 0; kg < 4; kg++) {
                ulonglong2 w0 = *reinterpret_cast<const ulonglong2*>(&wc[(kg * 4 + 0) * 512 + col0]);
                ulonglong2 w1 = *reinterpret_cast<const ulonglong2*>(&wc[(kg * 4 + 1) * 512 + col0]);
                ulonglong2 w2 = *reinterpret_cast<const ulonglong2*>(&wc[(kg * 4 + 2) * 512 + col0]);
                ulonglong2 w3 = *reinterpret_cast<const ulonglong2*>(&wc[(kg * 4 + 3) * 512 + col0]);
#pragma unroll
                for (int r = 0; r < 16; r++) {
                    float4 h4 = *reinterpret_cast<const float4*>(&hs[(rowbase + r) * 128 + ch * 16 + kg * 4]);
                    u64 hx = dup2(h4.x), hy = dup2(h4.y), hz = dup2(h4.z), hw = dup2(h4.w);
                    ffma2(acc[r][0], hx, w0.x); ffma2(acc[r][1], hx, w0.y);
                    ffma2(acc[r][0], hy, w1.x); ffma2(acc[r][1], hy, w1.y);
                    ffma2(acc[r][0], hz, w2.x); ffma2(acc[r][1], hz, w2.y);
                    ffma2(acc[r][0], hw, w3.x); ffma2(acc[r][1], hw, w3.y);
                }
            }
            CP_WAIT0;
            __syncthreads();
        }
#pragma unroll
        for (int r = 0; r < 16; r++) {
            ulonglong2 v; v.x = acc[r][0]; v.y = acc[r][1];
            *reinterpret_cast<ulonglong2*>(&gates[(rowbase + r) * 512 + col0]) = v;
        }
        __syncthreads();

        // -------- pointwise (thread owns row prow, cells pc0..pc0+15) --------
        {
            const int row = prow, n = n0 + row, len = slen[row];
            const int gi = dir ? min(max(len - 1 - s, 0), TSTEPS - 1) : s;
            float a4[4][16];
#pragma unroll
            for (int q = 0; q < 4; q++)
#pragma unroll
                for (int b = 0; b < 4; b++)
                    *reinterpret_cast<float4*>(&a4[q][b * 4]) =
                        *reinterpret_cast<const float4*>(&gates[row * 512 + q * 128 + pc0 + b * 4]);

            if (MODE == 0) {
                int id = idxmat[(size_t)gi * NSEQ + n];
                const float* grow = tab + (size_t)id * G4;
#pragma unroll
                for (int q = 0; q < 4; q++)
#pragma unroll
                    for (int b = 0; b < 4; b++) {
                        float4 g4 = *reinterpret_cast<const float4*>(&grow[q * 128 + pc0 + b * 4]);
                        a4[q][b * 4 + 0] += g4.x; a4[q][b * 4 + 1] += g4.y;
                        a4[q][b * 4 + 2] += g4.z; a4[q][b * 4 + 3] += g4.w;
                    }
            } else {
                int pl = idxmat[(size_t)gi * NSEQ + n];
                bool keep = (gi < sfe[row]) && (pl >= 0) && (pl < sun[row]);
                const float* grow = keep ? (tab + (size_t)min(pl + soff[row], NU - 1) * G4) : nullptr;
#pragma unroll
                for (int q = 0; q < 4; q++)
#pragma unroll
                    for (int b = 0; b < 4; b++) {
                        float4 b4 = *reinterpret_cast<const float4*>(&sbias[q * 128 + pc0 + b * 4]);
                        a4[q][b * 4 + 0] += b4.x; a4[q][b * 4 + 1] += b4.y;
                        a4[q][b * 4 + 2] += b4.z; a4[q][b * 4 + 3] += b4.w;
                        if (keep) {
                            float4 g4 = *reinterpret_cast<const float4*>(&grow[q * 128 + pc0 + b * 4]);
                            a4[q][b * 4 + 0] += g4.x; a4[q][b * 4 + 1] += g4.y;
                            a4[q][b * 4 + 2] += g4.z; a4[q][b * 4 + 3] += g4.w;
                        }
                    }
            }

            float hv[16];
#pragma unroll
            for (int j = 0; j < 16; j++) {
                float cn = sigm(a4[1][j]) * cst[j] + sigm(a4[0][j]) * tanhf(a4[2][j]);
                cst[j] = cn;
                hv[j] = sigm(a4[3][j]) * tanhf(cn);
            }
#pragma unroll
            for (int b = 0; b < 4; b++)
                *reinterpret_cast<float4*>(&hs[row * 128 + pc0 + b * 4]) =
                    make_float4(hv[b * 4], hv[b * 4 + 1], hv[b * 4 + 2], hv[b * 4 + 3]);

            __nv_bfloat162 hb[8], lb[8];
#pragma unroll
            for (int j = 0; j < 8; j++) {
                __nv_bfloat16 h0 = __float2bfloat16(hv[2 * j]), h1 = __float2bfloat16(hv[2 * j + 1]);
                hb[j] = __nv_bfloat162(h0, h1);
                lb[j] = __nv_bfloat162(__float2bfloat16(hv[2 * j] - __bfloat162float(h0)),
                                       __float2bfloat16(hv[2 * j + 1] - __bfloat162float(h1)));
            }
            if (s < len) {
                int wi = dir ? (len - 1 - s) : s;
                size_t base = ((size_t)wi * NSEQ + n) * (2 * HH) + dir * HH + pc0;
                *reinterpret_cast<uint4*>(Hh + base)     = *reinterpret_cast<uint4*>(hb);
                *reinterpret_cast<uint4*>(Hh + base + 8) = *reinterpret_cast<uint4*>(hb + 4);
                *reinterpret_cast<uint4*>(Hl + base)     = *reinterpret_cast<uint4*>(lb);
                *reinterpret_cast<uint4*>(Hl + base + 8) = *reinterpret_cast<uint4*>(lb + 4);
            } else if (dir == 0) {
                uint4 z = make_uint4(0u, 0u, 0u, 0u);
                size_t b0 = ((size_t)s * NSEQ + n) * (2 * HH) + pc0;
                *reinterpret_cast<uint4*>(Hh + b0) = z;       *reinterpret_cast<uint4*>(Hh + b0 + 8) = z;
                *reinterpret_cast<uint4*>(Hl + b0) = z;       *reinterpret_cast<uint4*>(Hl + b0 + 8) = z;
                *reinterpret_cast<uint4*>(Hh + b0 + HH) = z;  *reinterpret_cast<uint4*>(Hh + b0 + HH + 8) = z;
                *reinterpret_cast<uint4*>(Hl + b0 + HH) = z;  *reinterpret_cast<uint4*>(Hl + b0 + HH + 8) = z;
            }
        }
        __syncthreads();
    }
}

// ============ attention pooling ============
__global__ void k_attn(const float* __restrict__ ln_g, const float* __restrict__ ln_b,
                       const float* __restrict__ attn_w, const float* __restrict__ attn_bp) {
    int gwarp = (blockIdx.x * blockDim.x + threadIdx.x) >> 5;
    int lane = threadIdx.x & 31;
    if (gwarp >= NU) return;
    int n = gwarp, len = g_tok_len[n];
    float gg[4], bb[4], aw[4];
#pragma unroll
    for (int q = 0; q < 4; q++) {
        int e = lane + 32 * q;
        gg[q] = ln_g[e]; bb[q] = ln_b[e]; aw[q] = attn_w[e];
    }
    float ab = attn_bp[0];
    float sc[TT], smax = -1e30f;
#pragma unroll
    for (int t = 0; t < TT; t++) {
        sc[t] = -1e30f;
        if (t < len) {
            float o[4], lsum = 0.f;
#pragma unroll
            for (int q = 0; q < 4; q++) {
                o[q] = g_lin[((size_t)t * NU + n) * EE + lane + 32 * q];
                lsum += o[q];
            }
#pragma unroll
            for (int off = 16; off; off >>= 1) lsum += __shfl_xor_sync(0xffffffffu, lsum, off);
            float mean = lsum * (1.f / 128.f);
            float vs = 0.f;
#pragma unroll
            for (int q = 0; q < 4; q++) { float d = o[q] - mean; vs += d * d; }
#pragma unroll
            for (int off = 16; off; off >>= 1) vs += __shfl_xor_sync(0xffffffffu, vs, off);
            float inv = rsqrtf(vs * (1.f / 128.f) + 1e-5f);
            float ssum = 0.f;
#pragma unroll
            for (int q = 0; q < 4; q++)
                ssum += tanhf((o[q] - mean) * inv * gg[q] + bb[q]) * aw[q];
#pragma unroll
            for (int off = 16; off; off >>= 1) ssum += __shfl_xor_sync(0xffffffffu, ssum, off);
            sc[t] = ssum + ab;
            smax = fmaxf(smax, sc[t]);
        }
    }
    float den = 0.f, wts[TT];
#pragma unroll
    for (int t = 0; t < TT; t++) {
        wts[t] = (t < len) ? expf(sc[t] - smax) : 0.f;
        den += wts[t];
    }
    float invden = 1.f / den;
    float accq[4] = {0.f, 0.f, 0.f, 0.f};
#pragma unroll
    for (int t = 0; t < TT; t++) {
        if (t < len) {
            float wt = wts[t] * invden;
#pragma unroll
            for (int q = 0; q < 4; q++)
                accq[q] += wt * g_lin[((size_t)t * NU + n) * EE + lane + 32 * q];
        }
    }
#pragma unroll
    for (int q = 0; q < 4; q++) {
        __nv_bfloat16 h = __float2bfloat16(accq[q]);
        __nv_bfloat16 l = __float2bfloat16(accq[q] - __bfloat162float(h));
        g_tf_h[(size_t)n * EE + lane + 32 * q] = h;
        g_tf_l[(size_t)n * EE + lane + 32 * q] = l;
    }
}

// ============ host launcher ============
extern "C" void kernel_launch(void* const* d_in, const int* in_sizes, int n_in,
                              void* d_out, int out_size) {
    const int*   units  = (const int*)d_in[0];
    const int*   paths  = (const int*)d_in[1];
    const int*   upd    = (const int*)d_in[2];
    const int*   ppd    = (const int*)d_in[3];
    const float* emb    = (const float*)d_in[4];
    const float* tl_Wif = (const float*)d_in[5];
    const float* tl_Whf = (const float*)d_in[6];
    const float* tl_bf  = (const float*)d_in[7];
    const float* tl_Wib = (const float*)d_in[8];
    const float* tl_Whb = (const float*)d_in[9];
    const float* tl_bb  = (const float*)d_in[10];
    const float* lin_W  = (const float*)d_in[11];
    const float* lin_b  = (const float*)d_in[12];
    const float* ln_g   = (const float*)d_in[13];
    const float* ln_bv  = (const float*)d_in[14];
    const float* attn_w = (const float*)d_in[15];
    const float* attn_b = (const float*)d_in[16];
    const float* pl_Wif = (const float*)d_in[17];
    const float* pl_Whf = (const float*)d_in[18];
    const float* pl_bf  = (const float*)d_in[19];
    const float* pl_Wib = (const float*)d_in[20];
    const float* pl_Whb = (const float*)d_in[21];
    const float* pl_bb  = (const float*)d_in[22];
    const float* ul_W   = (const float*)d_in[23];
    const float* ul_b   = (const float*)d_in[24];
    float* out = (float*)d_out;

    void *pVTf, *pVTb, *pPTf, *pPTb, *pZero;
    cudaGetSymbolAddress(&pVTf, g_VTf);    cudaGetSymbolAddress(&pVTb, g_VTb);
    cudaGetSymbolAddress(&pPTf, g_PTf);    cudaGetSymbolAddress(&pPTb, g_PTb);
    cudaGetSymbolAddress(&pZero, g_zero);
    void *pEh, *pEl, *pHch, *pHcl, *pTfh, *pTfl, *pHph, *pHpl, *pWih, *pWil, *pW2h, *pW2l, *pLin;
    cudaGetSymbolAddress(&pLin, g_lin);
    cudaGetSymbolAddress(&pEh, g_emb_h);   cudaGetSymbolAddress(&pEl, g_emb_l);
    cudaGetSymbolAddress(&pHch, g_Hcat_h); cudaGetSymbolAddress(&pHcl, g_Hcat_l);
    cudaGetSymbolAddress(&pTfh, g_tf_h);   cudaGetSymbolAddress(&pTfl, g_tf_l);
    cudaGetSymbolAddress(&pHph, g_Hp_h);   cudaGetSymbolAddress(&pHpl, g_Hp_l);
    cudaGetSymbolAddress(&pWih, g_Wih);    cudaGetSymbolAddress(&pWil, g_Wil);
    cudaGetSymbolAddress(&pW2h, g_W2h);    cudaGetSymbolAddress(&pW2l, g_W2l);
    __nv_bfloat16* Wih = (__nv_bfloat16*)pWih;  __nv_bfloat16* Wil = (__nv_bfloat16*)pWil;
    __nv_bfloat16* W2h = (__nv_bfloat16*)pW2h;  __nv_bfloat16* W2l = (__nv_bfloat16*)pW2l;

    const int MM_SMEM = 4 * 128 * 72 * 2;
    const int LS_T = (32 * 512 + 32 * 128 + 2 * 8192) * 4 + 4 * 32 * 4;          // 147968
    const int LS_P = (16 * 512 + 16 * 128 + 2 * 8192 + 512) * 4 + 4 * 16 * 4;    // 108800
    cudaFuncSetAttribute(k_mm2<128>, cudaFuncAttributeMaxDynamicSharedMemorySize, MM_SMEM);
    cudaFuncSetAttribute(k_mm2<256>, cudaFuncAttributeMaxDynamicSharedMemorySize, MM_SMEM);
    cudaFuncSetAttribute((const void*)k_lstm<0, TT, NU, 32, 256>,
                         cudaFuncAttributeMaxDynamicSharedMemorySize, LS_T + 1024);
    cudaFuncSetAttribute((const void*)k_lstm<1, LPATH, NPATH, 16, 128>,
                         cudaFuncAttributeMaxDynamicSharedMemorySize, LS_P + 1024);

    k_tok_len<<<NU / 256, 256>>>(units);
    k_transpose4<<<dim3((G4 * HH + 255) / 256, 4), 256>>>(tl_Whf, tl_Whb, pl_Whf, pl_Whb);
    k_plen<<<NPATH / 256, 256>>>(paths, upd, ppd);

    k_hilo<<<(G4 * EE / 4 + 255) / 256, 256>>>(tl_Wif, Wih + 0 * G4 * EE, Wil + 0 * G4 * EE, G4 * EE / 4);
    k_hilo<<<(G4 * EE / 4 + 255) / 256, 256>>>(tl_Wib, Wih + 1 * G4 * EE, Wil + 1 * G4 * EE, G4 * EE / 4);
    k_hilo<<<(G4 * EE / 4 + 255) / 256, 256>>>(pl_Wif, Wih + 2 * G4 * EE, Wil + 2 * G4 * EE, G4 * EE / 4);
    k_hilo<<<(G4 * EE / 4 + 255) / 256, 256>>>(pl_Wib, Wih + 3 * G4 * EE, Wil + 3 * G4 * EE, G4 * EE / 4);
    k_hilo<<<(EE * 256 / 4 + 255) / 256, 256>>>(lin_W, W2h + 0, W2l + 0, EE * 256 / 4);
    k_hilo<<<(EE * 256 / 4 + 255) / 256, 256>>>(ul_W, W2h + EE * 256, W2l + EE * 256, EE * 256 / 4);
    k_hilo<<<(VOCAB * EE / 4 + 255) / 256, 256>>>(emb, (__nv_bfloat16*)pEh, (__nv_bfloat16*)pEl, VOCAB * EE / 4);

    k_mm2<128><<<dim3(4, VOCAB / 128), 256, MM_SMEM>>>((const __nv_bfloat16*)pEh, (const __nv_bfloat16*)pEl,
        Wih + 0 * G4 * EE, Wil + 0 * G4 * EE, tl_bf, (float*)pVTf, G4);
    k_mm2<128><<<dim3(4, VOCAB / 128), 256, MM_SMEM>>>((const __nv_bfloat16*)pEh, (const __nv_bfloat16*)pEl,
        Wih + 1 * G4 * EE, Wil + 1 * G4 * EE, tl_bb, (float*)pVTb, G4);

    k_lstm<0, TT, NU, 32, 256><<<dim3(NU / 32, 2), 256, LS_T>>>(
        units, (const float*)pVTf, (const float*)pVTb, nullptr, nullptr,
        (__nv_bfloat16*)pHch, (__nv_bfloat16*)pHcl);

    k_mm2<256><<<dim3(1, TT * NU / 128), 256, MM_SMEM>>>((const __nv_bfloat16*)pHch, (const __nv_bfloat16*)pHcl,
        W2h + 0, W2l + 0, lin_b, (float*)pLin, EE);

    k_attn<<<(NU * 32) / 256, 256>>>(ln_g, ln_bv, attn_w, attn_b);

    k_mm2<128><<<dim3(4, NU / 128), 256, MM_SMEM>>>((const __nv_bfloat16*)pTfh, (const __nv_bfloat16*)pTfl,
        Wih + 2 * G4 * EE, Wil + 2 * G4 * EE, (const float*)pZero, (float*)pPTf, G4);
    k_mm2<128><<<dim3(4, NU / 128), 256, MM_SMEM>>>((const __nv_bfloat16*)pTfh, (const __nv_bfloat16*)pTfl,
        Wih + 3 * G4 * EE, Wil + 3 * G4 * EE, (const float*)pZero, (float*)pPTb, G4);

    k_lstm<1, LPATH, NPATH, 16, 128><<<dim3(NPATH / 16, 2), 128, LS_P>>>(
        paths, (const float*)pPTf, (const float*)pPTb, pl_bf, pl_bb,
        (__nv_bfloat16*)pHph, (__nv_bfloat16*)pHpl);

    k_mm2<256><<<dim3(1, LPATH * NPATH / 128), 256, MM_SMEM>>>((const __nv_bfloat16*)pHph, (const __nv_bfloat16*)pHpl,
        W2h + EE * 256, W2l + EE * 256, ul_b, out, EE);
}